// round 16
// baseline (speedup 1.0000x reference)
#include <cuda_runtime.h>
#include <cuda_fp16.h>
#include <cstdint>
#include <cstddef>

// ============================================================================
// VAE_gamma on GB300. mma.sync m16n8k16.f16 (f32 acc).
// Encoder/heads: 2 products (exact weights x fp16 acts). Decoder: 1 product.
// Gamma sampler does a +-tau decision-stability test; unstable elements
// (expected ~200) are exactly recomputed via a gathered 512-row 3-product
// encoder chain and re-sampled before the decoder consumes z.
// ============================================================================

#define BATCHN   8192
#define LATENT   64
#define KROUNDS  24
#define GAMMA_N  524288u
#define MAXFLAG  512
#define TAU      4e-3f

// ---------------------------------------------------------------------------
// Scratch
// ---------------------------------------------------------------------------
__device__ alignas(16) __half g_xh [8192 * 2048];
__device__ alignas(16) __half g_xl [8192 * 2048];
__device__ alignas(16) __half g_b0h[8192 * 2048];
__device__ alignas(16) __half g_b1h[8192 * 2048];
__device__ alignas(16) __half g_zh [8192 * 64];
__device__ alignas(16) __half g_wh [12976128];
__device__ alignas(16) __half g_wl [12976128];
__device__ float g_pre[8192 * 256];     // two K-partials of the heads GEMM
__device__ float g_bh [128];
// fixup scratch
__device__ alignas(16) __half g_f1h[512 * 1024], g_f1l[512 * 1024];
__device__ alignas(16) __half g_f2h[512 * 1024], g_f2l[512 * 1024];
__device__ alignas(16) __half g_f3h[512 * 2048], g_f3l[512 * 2048];
__device__ float g_pref[512 * 128];
__device__ uint32_t g_nflag;
__device__ uint32_t g_flags[MAXFLAG];

#define OW1  0u                         // [1024][2048]
#define OW2  (OW1 + 2097152u)           // [1024][1024]
#define OW3  (OW2 + 1048576u)           // [2048][1024]
#define OWH  (OW3 + 2097152u)           // [128][2048]
#define OW4  (OWH + 262144u)            // [2048][64]
#define OW5  (OW4 + 131072u)            // [1024][2048]
#define OW6  (OW5 + 2097152u)           // [1024][1024]
#define OW7  (OW6 + 1048576u)           // [4096][1024]

// ---------------------------------------------------------------------------
// Threefry-2x32 (JAX partitionable mode)
// ---------------------------------------------------------------------------
constexpr unsigned rotlc(unsigned x, int r) { return (x << r) | (x >> (32 - r)); }
constexpr unsigned long long tf_const(unsigned k0, unsigned k1,
                                      unsigned x0, unsigned x1) {
    unsigned kx = k0 ^ k1 ^ 0x1BD11BDAu;
    unsigned ks[3] = {k0, k1, kx};
    const int R0[4] = {13, 15, 26, 6};
    const int R1[4] = {17, 29, 16, 24};
    x0 += k0; x1 += k1;
    for (int i = 0; i < 5; i++) {
        const int* rr = (i % 2 == 0) ? R0 : R1;
        for (int j = 0; j < 4; j++) { x0 += x1; x1 = rotlc(x1, rr[j]); x1 ^= x0; }
        x0 += ks[(i + 1) % 3];
        x1 += ks[(i + 2) % 3] + (unsigned)(i + 1);
    }
    return ((unsigned long long)x0 << 32) | x1;
}
constexpr unsigned long long SPN = tf_const(0u, 42u, 0u, 0u);
constexpr unsigned long long SPU = tf_const(0u, 42u, 0u, 1u);
constexpr unsigned KEY_N0 = (unsigned)(SPN >> 32);
constexpr unsigned KEY_N1 = (unsigned)(SPN & 0xFFFFFFFFu);
constexpr unsigned KEY_U0 = (unsigned)(SPU >> 32);
constexpr unsigned KEY_U1 = (unsigned)(SPU & 0xFFFFFFFFu);

__device__ __forceinline__ uint32_t rotl32(uint32_t x, int r) {
    return __funnelshift_l(x, x, r);
}
__device__ __forceinline__ void tf2x32(uint32_t k0, uint32_t k1,
                                       uint32_t x0, uint32_t x1,
                                       uint32_t& y0, uint32_t& y1) {
    uint32_t kx = k0 ^ k1 ^ 0x1BD11BDAu;
    x0 += k0; x1 += k1;
#define TF_RND(r) { x0 += x1; x1 = rotl32(x1, r); x1 ^= x0; }
    TF_RND(13) TF_RND(15) TF_RND(26) TF_RND(6)   x0 += k1; x1 += kx + 1u;
    TF_RND(17) TF_RND(29) TF_RND(16) TF_RND(24)  x0 += kx; x1 += k0 + 2u;
    TF_RND(13) TF_RND(15) TF_RND(26) TF_RND(6)   x0 += k0; x1 += k1 + 3u;
    TF_RND(17) TF_RND(29) TF_RND(16) TF_RND(24)  x0 += k1; x1 += kx + 4u;
    TF_RND(13) TF_RND(15) TF_RND(26) TF_RND(6)   x0 += kx; x1 += k0 + 5u;
#undef TF_RND
    y0 = x0; y1 = x1;
}
__device__ __forceinline__ uint32_t gamma_bits(uint32_t k0, uint32_t k1,
                                               uint32_t idx) {
    uint32_t y0, y1;
    tf2x32(k0, k1, 0u, idx, y0, y1);
    return y0 ^ y1;
}
__device__ __forceinline__ float bits_to_u01(uint32_t bits) {
    return __uint_as_float((bits >> 9) | 0x3F800000u) - 1.0f;
}
__device__ __forceinline__ float erfinv_xla(float x) {
    float w = -log1pf(-__fmul_rn(x, x));
    float p;
    if (w < 5.0f) {
        w = __fadd_rn(w, -2.5f);
        p = 2.81022636e-08f;
        p = __fadd_rn(__fmul_rn(p, w),  3.43273939e-07f);
        p = __fadd_rn(__fmul_rn(p, w), -3.5233877e-06f);
        p = __fadd_rn(__fmul_rn(p, w), -4.39150654e-06f);
        p = __fadd_rn(__fmul_rn(p, w),  0.00021858087f);
        p = __fadd_rn(__fmul_rn(p, w), -0.00125372503f);
        p = __fadd_rn(__fmul_rn(p, w), -0.00417768164f);
        p = __fadd_rn(__fmul_rn(p, w),  0.246640727f);
        p = __fadd_rn(__fmul_rn(p, w),  1.50140941f);
    } else {
        w = __fadd_rn(__fsqrt_rn(w), -3.0f);
        p = -0.000200214257f;
        p = __fadd_rn(__fmul_rn(p, w),  0.000100950558f);
        p = __fadd_rn(__fmul_rn(p, w),  0.00134934322f);
        p = __fadd_rn(__fmul_rn(p, w), -0.00367342844f);
        p = __fadd_rn(__fmul_rn(p, w),  0.00573950773f);
        p = __fadd_rn(__fmul_rn(p, w), -0.0076224613f);
        p = __fadd_rn(__fmul_rn(p, w),  0.00943887047f);
        p = __fadd_rn(__fmul_rn(p, w),  1.00167406f);
        p = __fadd_rn(__fmul_rn(p, w),  2.83297682f);
    }
    return __fmul_rn(p, x);
}
__device__ __forceinline__ float softplusf(float x) {
    return __fadd_rn(fmaxf(x, 0.0f), log1pf(expf(-fabsf(x))));
}

// Exact single-track sampler (original math/order).
__device__ __forceinline__ void gamma_exact(float preA, float preB, uint32_t i,
                                            float& oal, float& obe, float& oz) {
    float al = __fadd_rn(1e-6f, softplusf(preA));
    float be = __fadd_rn(1e-6f, softplusf(preB));
    float d  = __fadd_rn(__fadd_rn(al, 1.0f), -(1.0f / 3.0f));
    float cc = __fdiv_rn(1.0f, __fsqrt_rn(__fmul_rn(9.0f, d)));

    const float LO = -0.99999994f, SPAN_N = 2.0f;
    const float UMIN = 1e-7f, SPAN_U = 1.0f - 1e-7f, SQRT2 = 1.41421356f;

    float eps_s = 0.0f, u_s = 0.0f, eps0 = 0.0f, u0 = 0.0f;
    bool found = false;
#pragma unroll 1
    for (int k = 0; k < KROUNDS; ++k) {
        uint32_t idx = (uint32_t)k * GAMMA_N + i;
        uint32_t bn = gamma_bits(KEY_N0, KEY_N1, idx);
        uint32_t bu = gamma_bits(KEY_U0, KEY_U1, idx);
        float un = __fadd_rn(__fmul_rn(bits_to_u01(bn), SPAN_N), LO);
        un = fmaxf(LO, un);
        float eps = __fmul_rn(SQRT2, erfinv_xla(un));
        float uu = __fadd_rn(__fmul_rn(bits_to_u01(bu), SPAN_U), UMIN);
        uu = fmaxf(UMIN, uu);
        if (k == 0) { eps0 = eps; u0 = uu; }
        float v = __fadd_rn(1.0f, __fmul_rn(cc, eps));
        bool acc = false;
        if (v > 0.0f) {
            float e2 = __fmul_rn(eps, eps);
            float squeeze = __fadd_rn(1.0f, -__fmul_rn(__fmul_rn(0.0331f, e2), e2));
            if (uu < squeeze) acc = true;
            else {
                float v3 = __fmul_rn(__fmul_rn(v, v), v);
                float inner = __fadd_rn(__fadd_rn(1.0f, -v3), logf(v3));
                float rhs = __fadd_rn(__fmul_rn(__fmul_rn(0.5f, eps), eps),
                                      __fmul_rn(d, inner));
                if (logf(uu) < rhs) acc = true;
            }
        }
        if (acc) { eps_s = eps; u_s = uu; found = true; break; }
    }
    if (!found) { eps_s = eps0; u_s = u0; }
    float v1 = __fadd_rn(1.0f, __fmul_rn(cc, eps_s));
    float vs = __fmul_rn(v1, __fmul_rn(v1, v1));
    float t1 = logf(__fadd_rn(__fmul_rn(d, vs), 1e-6f));
    float t2 = __fdiv_rn(logf(__fadd_rn(u_s, 1e-6f)), __fadd_rn(al, 1e-6f));
    oz = __fdiv_rn(expf(__fadd_rn(t1, t2)), __fadd_rn(be, 1e-6f));
    oal = al; obe = be;
}

// ---------------------------------------------------------------------------
// mma / ldmatrix / cp.async helpers
// ---------------------------------------------------------------------------
__device__ __forceinline__ uint32_t smem_u32(const void* p) {
    uint32_t a;
    asm("{ .reg .u64 t; cvta.to.shared.u64 t, %1; cvt.u32.u64 %0, t; }"
        : "=r"(a) : "l"(p));
    return a;
}
__device__ __forceinline__ void mma_f16(float* c, const uint32_t* a,
                                        const uint32_t* b) {
    asm volatile(
        "mma.sync.aligned.m16n8k16.row.col.f32.f16.f16.f32 "
        "{%0,%1,%2,%3}, {%4,%5,%6,%7}, {%8,%9}, {%0,%1,%2,%3};"
        : "+f"(c[0]), "+f"(c[1]), "+f"(c[2]), "+f"(c[3])
        : "r"(a[0]), "r"(a[1]), "r"(a[2]), "r"(a[3]),
          "r"(b[0]), "r"(b[1]));
}
__device__ __forceinline__ void ldsm4(uint32_t& r0, uint32_t& r1,
                                      uint32_t& r2, uint32_t& r3, uint32_t a) {
    asm volatile("ldmatrix.sync.aligned.m8n8.x4.shared.b16 {%0,%1,%2,%3}, [%4];"
                 : "=r"(r0), "=r"(r1), "=r"(r2), "=r"(r3) : "r"(a));
}
__device__ __forceinline__ void cpa16(uint32_t dst, const void* src) {
    asm volatile("cp.async.cg.shared.global [%0], [%1], 16;"
                 :: "r"(dst), "l"(src));
}
__device__ __forceinline__ void split_h2(float x, float y,
                                         __half2& hi, __half2& lo) {
    hi = __floats2half2_rn(x, y);
    float2 b = __half22float2(hi);
    lo = __floats2half2_rn(__fadd_rn(x, -b.x), __fadd_rn(y, -b.y));
}
__device__ __forceinline__ uint32_t swz(int row, int q) {
    return (uint32_t)(((row >> 1) << 7) +
                      (((((row & 1) << 2) | q) ^ ((row >> 1) & 7)) << 4));
}

// ---------------------------------------------------------------------------
// GEMM: C[M,N] = act(A[M,K] @ Bt[N,K]^T + bias)
//   NPROD: 3 = ah*bh+ah*bl+al*bh; 2 = ah*bh+ah*bl; 1 = ah*bh.
//   ACT: 0 fp32 (bias unless SPLITK); 1 relu half hi (WRLO: +lo); 2 softplus.
//   IDX: gather A rows through g_flags (element>>6, clamped).
// ---------------------------------------------------------------------------
#define PLANEB 8192
#define STAGEB (4 * PLANEB)
#define NSTAGE 3

template <int ACT, int NPROD, int WRLO, int SPLITK, int IDX>
__global__ __launch_bounds__(256, 2)
void mma_gemm(const __half* __restrict__ Ahg, const __half* __restrict__ Alg,
              const __half* __restrict__ Bhg, const __half* __restrict__ Blg,
              const float* __restrict__ bias,
              __half* __restrict__ Chg, __half* __restrict__ Clg,
              float* __restrict__ C, float* __restrict__ C2,
              int K, int lda, int ldc) {
    extern __shared__ __half smh[];
    __shared__ float s_bias[128];

    const int tid  = threadIdx.x;
    const int wid  = tid >> 5;
    const int lane = tid & 31;
    const int qr   = lane >> 2;
    const int qc   = lane & 3;
    const int grp  = lane >> 3;
    const int lr   = lane & 7;
    const int m_w  = (wid >> 2) * 64;
    const int n_w  = (wid & 3) * 32;
    const int row0 = blockIdx.y * 128;
    const int col0 = blockIdx.x * 128;
    const int kb   = SPLITK ? ((int)blockIdx.z * K) : 0;

    if (tid < 128) s_bias[tid] = bias[col0 + tid];

    const uint32_t smb = smem_u32(smh);

    float acc[4][4][4];
#pragma unroll
    for (int a = 0; a < 4; ++a)
#pragma unroll
        for (int b = 0; b < 4; ++b)
#pragma unroll
            for (int c = 0; c < 4; ++c) acc[a][b][c] = 0.0f;

    const int NCH  = K >> 5;
    const int r_ld = tid >> 1;
    const int q0   = (tid & 1) * 2;

    int growA;
    if (IDX) {
        uint32_t fe = g_flags[row0 + r_ld];
        growA = min((int)(fe >> 6), 8191);
    } else {
        growA = row0 + r_ld;
    }
    const int growB = col0 + r_ld;
    const uint32_t d_sw0 = swz(r_ld, q0);
    const uint32_t d_sw1 = swz(r_ld, q0 + 1);

    auto issue = [&](int stage, int kchunk) {
        const int k0 = kb + (kchunk << 5);
        const uint32_t sbase = smb + (uint32_t)(stage * STAGEB);
        {
            const __half* s = Ahg + (size_t)growA * lda + k0 + q0 * 8;
            cpa16(sbase + d_sw0, s);
            cpa16(sbase + d_sw1, s + 8);
        }
        if (NPROD == 3) {
            const __half* s = Alg + (size_t)growA * lda + k0 + q0 * 8;
            cpa16(sbase + (uint32_t)PLANEB + d_sw0, s);
            cpa16(sbase + (uint32_t)PLANEB + d_sw1, s + 8);
        }
        {
            const __half* s = Bhg + (size_t)growB * lda + k0 + q0 * 8;
            cpa16(sbase + (uint32_t)(2 * PLANEB) + d_sw0, s);
            cpa16(sbase + (uint32_t)(2 * PLANEB) + d_sw1, s + 8);
        }
        if (NPROD >= 2) {
            const __half* s = Blg + (size_t)growB * lda + k0 + q0 * 8;
            cpa16(sbase + (uint32_t)(3 * PLANEB) + d_sw0, s);
            cpa16(sbase + (uint32_t)(3 * PLANEB) + d_sw1, s + 8);
        }
        asm volatile("cp.async.commit_group;" ::: "memory");
    };

    issue(0, 0);
    if (NCH > 1) {
        issue(1, 1);
        asm volatile("cp.async.wait_group 1;" ::: "memory");
    } else {
        asm volatile("cp.async.wait_group 0;" ::: "memory");
    }
    __syncthreads();

    for (int i = 0; i < NCH; ++i) {
        if (i + 2 < NCH) issue((i + 2) % NSTAGE, i + 2);

        const uint32_t sb = smb + (uint32_t)((i % NSTAGE) * STAGEB);
#pragma unroll
        for (int ks = 0; ks < 2; ++ks) {
            uint32_t bh[4][2], bl[4][2];
#pragma unroll
            for (int nn = 0; nn < 2; ++nn) {
                const int rB = n_w + nn * 16 + (grp >> 1) * 8 + lr;
                const int qB = ks * 2 + (grp & 1);
                const uint32_t ab = sb + (uint32_t)(2 * PLANEB) + swz(rB, qB);
                ldsm4(bh[2 * nn][0], bh[2 * nn][1],
                      bh[2 * nn + 1][0], bh[2 * nn + 1][1], ab);
                if (NPROD >= 2)
                    ldsm4(bl[2 * nn][0], bl[2 * nn][1],
                          bl[2 * nn + 1][0], bl[2 * nn + 1][1],
                          ab + (uint32_t)PLANEB);
            }
#pragma unroll
            for (int mt = 0; mt < 4; ++mt) {
                uint32_t ah[4], al[4];
                const int rA = m_w + mt * 16 + (grp & 1) * 8 + lr;
                const int qA = ks * 2 + (grp >> 1);
                const uint32_t aa = sb + swz(rA, qA);
                ldsm4(ah[0], ah[1], ah[2], ah[3], aa);
                if (NPROD == 3)
                    ldsm4(al[0], al[1], al[2], al[3], aa + (uint32_t)PLANEB);
#pragma unroll
                for (int nt = 0; nt < 4; ++nt) {
                    mma_f16(acc[mt][nt], ah, bh[nt]);
                    if (NPROD >= 2) mma_f16(acc[mt][nt], ah, bl[nt]);
                    if (NPROD == 3) mma_f16(acc[mt][nt], al, bh[nt]);
                }
            }
        }

        if (i + 1 < NCH) {
            if (i + 2 < NCH) {
                asm volatile("cp.async.wait_group 1;" ::: "memory");
            } else {
                asm volatile("cp.async.wait_group 0;" ::: "memory");
            }
            __syncthreads();
        }
    }

    float* Cz = SPLITK ? (C + (size_t)blockIdx.z * (8192ull * 128)) : C;
#pragma unroll
    for (int mt = 0; mt < 4; ++mt) {
        int r = row0 + m_w + mt * 16 + qr;
#pragma unroll
        for (int nt = 0; nt < 4; ++nt) {
            int lc = n_w + nt * 8 + 2 * qc;
            int gc = col0 + lc;
            float2 t0, t1;
            float b0v = SPLITK ? 0.0f : s_bias[lc];
            float b1v = SPLITK ? 0.0f : s_bias[lc + 1];
            t0.x = acc[mt][nt][0] + b0v;
            t0.y = acc[mt][nt][1] + b1v;
            t1.x = acc[mt][nt][2] + b0v;
            t1.y = acc[mt][nt][3] + b1v;
            if (ACT == 1) {
                t0.x = fmaxf(t0.x, 0.0f); t0.y = fmaxf(t0.y, 0.0f);
                t1.x = fmaxf(t1.x, 0.0f); t1.y = fmaxf(t1.y, 0.0f);
                if (WRLO) {
                    __half2 h2, l2;
                    split_h2(t0.x, t0.y, h2, l2);
                    *reinterpret_cast<__half2*>(&Chg[(size_t)r * ldc + gc]) = h2;
                    *reinterpret_cast<__half2*>(&Clg[(size_t)r * ldc + gc]) = l2;
                    split_h2(t1.x, t1.y, h2, l2);
                    *reinterpret_cast<__half2*>(&Chg[(size_t)(r + 8) * ldc + gc]) = h2;
                    *reinterpret_cast<__half2*>(&Clg[(size_t)(r + 8) * ldc + gc]) = l2;
                } else {
                    *reinterpret_cast<__half2*>(&Chg[(size_t)r * ldc + gc]) =
                        __floats2half2_rn(t0.x, t0.y);
                    *reinterpret_cast<__half2*>(&Chg[(size_t)(r + 8) * ldc + gc]) =
                        __floats2half2_rn(t1.x, t1.y);
                }
            } else if (ACT == 2) {
                t0.x = __fadd_rn(1e-6f, softplusf(t0.x));
                t0.y = __fadd_rn(1e-6f, softplusf(t0.y));
                t1.x = __fadd_rn(1e-6f, softplusf(t1.x));
                t1.y = __fadd_rn(1e-6f, softplusf(t1.y));
                if (gc < 2048) {
                    *reinterpret_cast<float2*>(&C [(size_t)r * 2048 + gc]) = t0;
                    *reinterpret_cast<float2*>(&C [(size_t)(r + 8) * 2048 + gc]) = t1;
                } else {
                    *reinterpret_cast<float2*>(&C2[(size_t)r * 2048 + gc - 2048]) = t0;
                    *reinterpret_cast<float2*>(&C2[(size_t)(r + 8) * 2048 + gc - 2048]) = t1;
                }
            } else {
                *reinterpret_cast<float2*>(&Cz[(size_t)r * ldc + gc]) = t0;
                *reinterpret_cast<float2*>(&Cz[(size_t)(r + 8) * ldc + gc]) = t1;
            }
        }
    }
}

// ---------------------------------------------------------------------------
// Merged prep: weights + x-split + bias + flag reset.
// ---------------------------------------------------------------------------
struct PrepJobs {
    const float* W[9];
    __half* Wh[9];
    __half* Wl[9];
    int K[9], N[9], start[9], wl[9];
    int wtiles;
    const float* X;
    __half* Xh; __half* Xl;
    int xblocks;
    const float* hb1; const float* hb2;
    float* bh;
};

__global__ __launch_bounds__(256)
void prep_all(PrepJobs j) {
    int b = blockIdx.x;
    if (b < j.wtiles) {
        int ji = 0;
#pragma unroll
        for (int s = 1; s < 9; ++s)
            if (b >= j.start[s]) ji = s;
        const float* W = j.W[ji];
        __half* Wh = j.Wh[ji];
        __half* Wl = j.Wl[ji];
        int K = j.K[ji], N = j.N[ji];
        int wl = j.wl[ji];
        int t = b - j.start[ji];
        int ntn = N >> 5;
        int n0 = (t % ntn) << 5, k0 = (t / ntn) << 5;

        __shared__ float s[32][33];
        int tt = threadIdx.x;
        int a = tt >> 5, bb = tt & 31;
#pragma unroll
        for (int p = 0; p < 4; ++p) {
            int k = p * 8 + a;
            s[k][bb] = W[(size_t)(k0 + k) * N + n0 + bb];
        }
        __syncthreads();
#pragma unroll
        for (int p = 0; p < 4; ++p) {
            int n = p * 8 + a;
            float v = s[bb][n];
            __half h = __float2half_rn(v);
            Wh[(size_t)(n0 + n) * K + k0 + bb] = h;
            if (wl)
                Wl[(size_t)(n0 + n) * K + k0 + bb] =
                    __float2half_rn(__fadd_rn(v, -__half2float(h)));
        }
        return;
    }
    b -= j.wtiles;
    if (b < j.xblocks) {
        int t = b * 256 + threadIdx.x;
        float4 v = reinterpret_cast<const float4*>(j.X)[t];
        __half2 h0, l0, h1, l1;
        split_h2(v.x, v.y, h0, l0);
        split_h2(v.z, v.w, h1, l1);
        reinterpret_cast<__half2*>(j.Xh)[2 * t]     = h0;
        reinterpret_cast<__half2*>(j.Xh)[2 * t + 1] = h1;
        reinterpret_cast<__half2*>(j.Xl)[2 * t]     = l0;
        reinterpret_cast<__half2*>(j.Xl)[2 * t + 1] = l1;
        return;
    }
    // last block: bias concat + flag reset
    int t = threadIdx.x;
    if (t < 128) j.bh[t] = (t < 64) ? j.hb1[t] : j.hb2[t - 64];
    g_flags[t] = 0u;
    g_flags[t + 256] = 0u;
    if (t == 0) g_nflag = 0u;
}

// ---------------------------------------------------------------------------
// Gamma sampler with +-tau decision-stability test.
// ---------------------------------------------------------------------------
__global__ __launch_bounds__(256)
void gamma_sampler(const float* __restrict__ pre, const float* __restrict__ bh,
                   float* __restrict__ out_la, float* __restrict__ out_lb,
                   float* __restrict__ out_z, __half* __restrict__ zh) {
    int i = blockIdx.x * blockDim.x + threadIdx.x;
    if (i >= BATCHN * LATENT) return;
    int row = i >> 6, lat = i & 63;

    const float* p1 = pre + 8192ull * 128;
    float preA = (pre[row * 128 + lat]      + p1[row * 128 + lat])      + bh[lat];
    float preB = (pre[row * 128 + 64 + lat] + p1[row * 128 + 64 + lat]) + bh[64 + lat];

    float al3[3], d3[3], cc3[3];
    al3[0] = __fadd_rn(1e-6f, softplusf(preA - TAU));
    al3[1] = __fadd_rn(1e-6f, softplusf(preA));
    al3[2] = __fadd_rn(1e-6f, softplusf(preA + TAU));
#pragma unroll
    for (int t = 0; t < 3; ++t) {
        d3[t]  = __fadd_rn(__fadd_rn(al3[t], 1.0f), -(1.0f / 3.0f));
        cc3[t] = __fdiv_rn(1.0f, __fsqrt_rn(__fmul_rn(9.0f, d3[t])));
    }
    float be = __fadd_rn(1e-6f, softplusf(preB));

    const float LO = -0.99999994f, SPAN_N = 2.0f;
    const float UMIN = 1e-7f, SPAN_U = 1.0f - 1e-7f, SQRT2 = 1.41421356f;

    int kk[3] = {-1, -1, -1};
    float es1 = 0.0f, us1 = 0.0f, eps0 = 0.0f, u0 = 0.0f;

#pragma unroll 1
    for (int k = 0; k < KROUNDS; ++k) {
        if (kk[0] >= 0 && kk[1] >= 0 && kk[2] >= 0) break;
        uint32_t idx = (uint32_t)k * GAMMA_N + (uint32_t)i;
        uint32_t bn = gamma_bits(KEY_N0, KEY_N1, idx);
        uint32_t bu = gamma_bits(KEY_U0, KEY_U1, idx);

        float un = __fadd_rn(__fmul_rn(bits_to_u01(bn), SPAN_N), LO);
        un = fmaxf(LO, un);
        float eps = __fmul_rn(SQRT2, erfinv_xla(un));
        float uu = __fadd_rn(__fmul_rn(bits_to_u01(bu), SPAN_U), UMIN);
        uu = fmaxf(UMIN, uu);
        if (k == 0) { eps0 = eps; u0 = uu; }

        float e2 = __fmul_rn(eps, eps);
        float squeeze = __fadd_rn(1.0f, -__fmul_rn(__fmul_rn(0.0331f, e2), e2));
        float lu = logf(uu);
#pragma unroll
        for (int t = 0; t < 3; ++t) {
            if (kk[t] >= 0) continue;
            float v = __fadd_rn(1.0f, __fmul_rn(cc3[t], eps));
            bool acc = false;
            if (v > 0.0f) {
                if (uu < squeeze) acc = true;
                else {
                    float v3 = __fmul_rn(__fmul_rn(v, v), v);
                    float inner = __fadd_rn(__fadd_rn(1.0f, -v3), logf(v3));
                    float rhs = __fadd_rn(__fmul_rn(__fmul_rn(0.5f, eps), eps),
                                          __fmul_rn(d3[t], inner));
                    if (lu < rhs) acc = true;
                }
            }
            if (acc) {
                kk[t] = k;
                if (t == 1) { es1 = eps; us1 = uu; }
            }
        }
    }

    float eps_s, u_s;
    if (kk[1] >= 0) { eps_s = es1; u_s = us1; }
    else            { eps_s = eps0; u_s = u0; }

    float v1 = __fadd_rn(1.0f, __fmul_rn(cc3[1], eps_s));
    float vs = __fmul_rn(v1, __fmul_rn(v1, v1));
    float t1 = logf(__fadd_rn(__fmul_rn(d3[1], vs), 1e-6f));
    float t2 = __fdiv_rn(logf(__fadd_rn(u_s, 1e-6f)), __fadd_rn(al3[1], 1e-6f));
    float z  = __fdiv_rn(expf(__fadd_rn(t1, t2)), __fadd_rn(be, 1e-6f));

    out_la[i] = al3[1];
    out_lb[i] = be;
    out_z[i]  = z;
    zh[i] = __float2half_rn(z);

    if (!(kk[0] == kk[1] && kk[1] == kk[2])) {
        uint32_t pos = atomicAdd(&g_nflag, 1u);
        if (pos < MAXFLAG) g_flags[pos] = (uint32_t)i;
    }
}

// Fixup sampler: exact preA/preB for flagged elements, overwrite outputs.
__global__ __launch_bounds__(256)
void fixup_sampler(const float* __restrict__ pref,
                   float* __restrict__ out_la, float* __restrict__ out_lb,
                   float* __restrict__ out_z, __half* __restrict__ zh) {
    uint32_t pos = blockIdx.x * 256 + threadIdx.x;
    uint32_t n = g_nflag;
    if (n > MAXFLAG) n = MAXFLAG;
    if (pos >= n) return;
    uint32_t i = g_flags[pos];
    int lat = (int)(i & 63u);
    float preA = pref[pos * 128 + lat];
    float preB = pref[pos * 128 + 64 + lat];
    float al, be, z;
    gamma_exact(preA, preB, i, al, be, z);
    out_la[i] = al;
    out_lb[i] = be;
    out_z[i]  = z;
    zh[i] = __float2half_rn(z);
}

// ---------------------------------------------------------------------------
// Launch
// ---------------------------------------------------------------------------
extern "C" void kernel_launch(void* const* d_in, const int* in_sizes, int n_in,
                              void* d_out, int out_size) {
    (void)in_sizes; (void)n_in; (void)out_size;

    const float* x    = (const float*)d_in[0];
    const float* f1w  = (const float*)d_in[1];
    const float* f1b  = (const float*)d_in[2];
    const float* f2w  = (const float*)d_in[3];
    const float* f2b  = (const float*)d_in[4];
    const float* f3w  = (const float*)d_in[5];
    const float* f3b  = (const float*)d_in[6];
    const float* f41w = (const float*)d_in[7];
    const float* f41b = (const float*)d_in[8];
    const float* f42w = (const float*)d_in[9];
    const float* f42b = (const float*)d_in[10];
    const float* f4w  = (const float*)d_in[11];
    const float* f4b  = (const float*)d_in[12];
    const float* f5w  = (const float*)d_in[13];
    const float* f5b  = (const float*)d_in[14];
    const float* f6w  = (const float*)d_in[15];
    const float* f6b  = (const float*)d_in[16];
    const float* f7w  = (const float*)d_in[17];
    const float* f7b  = (const float*)d_in[18];

    float* out = (float*)d_out;
    const size_t OFF_BE = 8192ull * 2048;
    const size_t OFF_LA = 2 * OFF_BE;
    const size_t OFF_LB = OFF_LA + 524288;
    const size_t OFF_Z  = OFF_LB + 524288;

    __half *xh, *xl, *b0h, *b1h, *zh, *wh, *wl;
    __half *f1h, *f1l, *f2h, *f2l, *f3h, *f3l;
    float *pre, *bh, *pref;
    cudaGetSymbolAddress((void**)&xh,  g_xh);
    cudaGetSymbolAddress((void**)&xl,  g_xl);
    cudaGetSymbolAddress((void**)&b0h, g_b0h);
    cudaGetSymbolAddress((void**)&b1h, g_b1h);
    cudaGetSymbolAddress((void**)&zh,  g_zh);
    cudaGetSymbolAddress((void**)&wh,  g_wh);
    cudaGetSymbolAddress((void**)&wl,  g_wl);
    cudaGetSymbolAddress((void**)&pre, g_pre);
    cudaGetSymbolAddress((void**)&bh,  g_bh);
    cudaGetSymbolAddress((void**)&f1h, g_f1h);
    cudaGetSymbolAddress((void**)&f1l, g_f1l);
    cudaGetSymbolAddress((void**)&f2h, g_f2h);
    cudaGetSymbolAddress((void**)&f2l, g_f2l);
    cudaGetSymbolAddress((void**)&f3h, g_f3h);
    cudaGetSymbolAddress((void**)&f3l, g_f3l);
    cudaGetSymbolAddress((void**)&pref, g_pref);

    constexpr int DYN = NSTAGE * STAGEB;   // 98304 bytes
    cudaFuncSetAttribute((const void*)mma_gemm<1, 2, 0, 0, 0>, cudaFuncAttributeMaxDynamicSharedMemorySize, DYN);
    cudaFuncSetAttribute((const void*)mma_gemm<0, 2, 0, 1, 0>, cudaFuncAttributeMaxDynamicSharedMemorySize, DYN);
    cudaFuncSetAttribute((const void*)mma_gemm<1, 3, 1, 0, 1>, cudaFuncAttributeMaxDynamicSharedMemorySize, DYN);
    cudaFuncSetAttribute((const void*)mma_gemm<1, 3, 1, 0, 0>, cudaFuncAttributeMaxDynamicSharedMemorySize, DYN);
    cudaFuncSetAttribute((const void*)mma_gemm<0, 3, 0, 0, 0>, cudaFuncAttributeMaxDynamicSharedMemorySize, DYN);
    cudaFuncSetAttribute((const void*)mma_gemm<1, 1, 0, 0, 0>, cudaFuncAttributeMaxDynamicSharedMemorySize, DYN);
    cudaFuncSetAttribute((const void*)mma_gemm<2, 1, 0, 0, 0>, cudaFuncAttributeMaxDynamicSharedMemorySize, DYN);

    // ---- merged prep ----
    PrepJobs jp = {};
    int st = 0;
    auto add = [&](int idx, const float* W, uint32_t off, int K, int N, int wlf) {
        jp.W[idx] = W; jp.Wh[idx] = wh + off; jp.Wl[idx] = wl + off;
        jp.K[idx] = K; jp.N[idx] = N; jp.start[idx] = st; jp.wl[idx] = wlf;
        st += (N >> 5) * (K >> 5);
    };
    add(0, f1w,  OW1, 2048, 1024, 1);
    add(1, f2w,  OW2, 1024, 1024, 1);
    add(2, f3w,  OW3, 1024, 2048, 1);
    add(3, f41w, OWH, 2048, 64,   1);
    add(4, f42w, OWH + 64 * 2048, 2048, 64, 1);
    add(5, f4w,  OW4, 64,   2048, 0);
    add(6, f5w,  OW5, 2048, 1024, 0);
    add(7, f6w,  OW6, 1024, 1024, 0);
    add(8, f7w,  OW7, 1024, 4096, 0);
    jp.wtiles = st;
    jp.X = x; jp.Xh = xh; jp.Xl = xl;
    jp.xblocks = (8192 * 2048 / 4) / 256;
    jp.hb1 = f41b; jp.hb2 = f42b; jp.bh = bh;
    prep_all<<<jp.wtiles + jp.xblocks + 1, 256>>>(jp);

    // ---- encoder (2-product: exact weights x fp16 activations) ----
    mma_gemm<1, 2, 0, 0, 0><<<dim3( 8, 64), 256, DYN>>>(xh,  nullptr, wh + OW1, wl + OW1, f1b, b0h, nullptr, nullptr, nullptr, 2048, 2048, 1024);
    mma_gemm<1, 2, 0, 0, 0><<<dim3( 8, 64), 256, DYN>>>(b0h, nullptr, wh + OW2, wl + OW2, f2b, b1h, nullptr, nullptr, nullptr, 1024, 1024, 1024);
    mma_gemm<1, 2, 0, 0, 0><<<dim3(16, 64), 256, DYN>>>(b1h, nullptr, wh + OW3, wl + OW3, f3b, b0h, nullptr, nullptr, nullptr, 1024, 1024, 2048);
    // heads split-K=2 (2-product) -> pre partials
    mma_gemm<0, 2, 0, 1, 0><<<dim3(1, 64, 2), 256, DYN>>>(b0h, nullptr, wh + OWH, wl + OWH, bh, nullptr, nullptr, pre, nullptr, 1024, 2048, 128);
    // ---- gamma sampler with stability flagging ----
    gamma_sampler<<<(BATCHN * LATENT) / 256, 256>>>(
        pre, bh, out + OFF_LA, out + OFF_LB, out + OFF_Z, zh);
    // ---- fixup: 3-product gathered encoder chain over flagged rows ----
    mma_gemm<1, 3, 1, 0, 1><<<dim3( 8, 4), 256, DYN>>>(xh,  xl,  wh + OW1, wl + OW1, f1b, f1h, f1l, nullptr, nullptr, 2048, 2048, 1024);
    mma_gemm<1, 3, 1, 0, 0><<<dim3( 8, 4), 256, DYN>>>(f1h, f1l, wh + OW2, wl + OW2, f2b, f2h, f2l, nullptr, nullptr, 1024, 1024, 1024);
    mma_gemm<1, 3, 1, 0, 0><<<dim3(16, 4), 256, DYN>>>(f2h, f2l, wh + OW3, wl + OW3, f3b, f3h, f3l, nullptr, nullptr, 1024, 1024, 2048);
    mma_gemm<0, 3, 0, 0, 0><<<dim3( 1, 4), 256, DYN>>>(f3h, f3l, wh + OWH, wl + OWH, bh, nullptr, nullptr, pref, nullptr, 2048, 2048, 128);
    fixup_sampler<<<2, 256>>>(pref, out + OFF_LA, out + OFF_LB, out + OFF_Z, zh);
    // ---- decoder (1-product) ----
    mma_gemm<1, 1, 0, 0, 0><<<dim3(16, 64), 256, DYN>>>(zh,  nullptr, wh + OW4, nullptr, f4b, b1h, nullptr, nullptr, nullptr, 64, 64, 2048);
    mma_gemm<1, 1, 0, 0, 0><<<dim3( 8, 64), 256, DYN>>>(b1h, nullptr, wh + OW5, nullptr, f5b, b0h, nullptr, nullptr, nullptr, 2048, 2048, 1024);
    mma_gemm<1, 1, 0, 0, 0><<<dim3( 8, 64), 256, DYN>>>(b0h, nullptr, wh + OW6, nullptr, f6b, b1h, nullptr, nullptr, nullptr, 1024, 1024, 1024);
    mma_gemm<2, 1, 0, 0, 0><<<dim3(32, 64), 256, DYN>>>(b1h, nullptr, wh + OW7, nullptr, f7b, nullptr, nullptr, out, out + OFF_BE, 1024, 1024, 2048);
}

// round 17
// speedup vs baseline: 1.1197x; 1.1197x over previous
#include <cuda_runtime.h>
#include <cuda_fp16.h>
#include <cstdint>
#include <cstddef>

// ============================================================================
// VAE_gamma on GB300. mma.sync m16n8k16.f16 (f32 acc).
// Encoder/heads: 2 products (exact weights x fp16 acts). Decoder: 1 product.
// Gamma sampler: +-tau decision-stability test; unstable elements exactly
// recomputed via a gathered 3-product encoder chain (split-K to kill serial
// latency) and re-sampled before the decoder consumes z.
// ============================================================================

#define BATCHN   8192
#define LATENT   64
#define KROUNDS  24
#define GAMMA_N  524288u
#define MAXFLAG  512
#define TAU      4e-3f

// ---------------------------------------------------------------------------
// Scratch
// ---------------------------------------------------------------------------
__device__ alignas(16) __half g_xh [8192 * 2048];
__device__ alignas(16) __half g_xl [8192 * 2048];
__device__ alignas(16) __half g_b0h[8192 * 2048];
__device__ alignas(16) __half g_b1h[8192 * 2048];
__device__ alignas(16) __half g_zh [8192 * 64];
__device__ alignas(16) __half g_wh [12976128];
__device__ alignas(16) __half g_wl [12976128];
__device__ float g_pre[8192 * 256];     // two K-partials of the heads GEMM
__device__ float g_bh [128];
// fixup scratch
__device__ alignas(16) __half g_f1h[512 * 1024], g_f1l[512 * 1024];
__device__ alignas(16) __half g_f2h[512 * 1024], g_f2l[512 * 1024];
__device__ alignas(16) __half g_f3h[512 * 2048], g_f3l[512 * 2048];
__device__ float g_fxp[8 * 512 * 1024];   // split-K partials (reused per layer)
__device__ uint32_t g_nflag;
__device__ uint32_t g_flags[MAXFLAG];

#define OW1  0u                         // [1024][2048]
#define OW2  (OW1 + 2097152u)           // [1024][1024]
#define OW3  (OW2 + 1048576u)           // [2048][1024]
#define OWH  (OW3 + 2097152u)           // [128][2048]
#define OW4  (OWH + 262144u)            // [2048][64]
#define OW5  (OW4 + 131072u)            // [1024][2048]
#define OW6  (OW5 + 2097152u)           // [1024][1024]
#define OW7  (OW6 + 1048576u)           // [4096][1024]

// ---------------------------------------------------------------------------
// Threefry-2x32 (JAX partitionable mode)
// ---------------------------------------------------------------------------
constexpr unsigned rotlc(unsigned x, int r) { return (x << r) | (x >> (32 - r)); }
constexpr unsigned long long tf_const(unsigned k0, unsigned k1,
                                      unsigned x0, unsigned x1) {
    unsigned kx = k0 ^ k1 ^ 0x1BD11BDAu;
    unsigned ks[3] = {k0, k1, kx};
    const int R0[4] = {13, 15, 26, 6};
    const int R1[4] = {17, 29, 16, 24};
    x0 += k0; x1 += k1;
    for (int i = 0; i < 5; i++) {
        const int* rr = (i % 2 == 0) ? R0 : R1;
        for (int j = 0; j < 4; j++) { x0 += x1; x1 = rotlc(x1, rr[j]); x1 ^= x0; }
        x0 += ks[(i + 1) % 3];
        x1 += ks[(i + 2) % 3] + (unsigned)(i + 1);
    }
    return ((unsigned long long)x0 << 32) | x1;
}
constexpr unsigned long long SPN = tf_const(0u, 42u, 0u, 0u);
constexpr unsigned long long SPU = tf_const(0u, 42u, 0u, 1u);
constexpr unsigned KEY_N0 = (unsigned)(SPN >> 32);
constexpr unsigned KEY_N1 = (unsigned)(SPN & 0xFFFFFFFFu);
constexpr unsigned KEY_U0 = (unsigned)(SPU >> 32);
constexpr unsigned KEY_U1 = (unsigned)(SPU & 0xFFFFFFFFu);

__device__ __forceinline__ uint32_t rotl32(uint32_t x, int r) {
    return __funnelshift_l(x, x, r);
}
__device__ __forceinline__ void tf2x32(uint32_t k0, uint32_t k1,
                                       uint32_t x0, uint32_t x1,
                                       uint32_t& y0, uint32_t& y1) {
    uint32_t kx = k0 ^ k1 ^ 0x1BD11BDAu;
    x0 += k0; x1 += k1;
#define TF_RND(r) { x0 += x1; x1 = rotl32(x1, r); x1 ^= x0; }
    TF_RND(13) TF_RND(15) TF_RND(26) TF_RND(6)   x0 += k1; x1 += kx + 1u;
    TF_RND(17) TF_RND(29) TF_RND(16) TF_RND(24)  x0 += kx; x1 += k0 + 2u;
    TF_RND(13) TF_RND(15) TF_RND(26) TF_RND(6)   x0 += k0; x1 += k1 + 3u;
    TF_RND(17) TF_RND(29) TF_RND(16) TF_RND(24)  x0 += k1; x1 += kx + 4u;
    TF_RND(13) TF_RND(15) TF_RND(26) TF_RND(6)   x0 += kx; x1 += k0 + 5u;
#undef TF_RND
    y0 = x0; y1 = x1;
}
__device__ __forceinline__ uint32_t gamma_bits(uint32_t k0, uint32_t k1,
                                               uint32_t idx) {
    uint32_t y0, y1;
    tf2x32(k0, k1, 0u, idx, y0, y1);
    return y0 ^ y1;
}
__device__ __forceinline__ float bits_to_u01(uint32_t bits) {
    return __uint_as_float((bits >> 9) | 0x3F800000u) - 1.0f;
}
__device__ __forceinline__ float erfinv_xla(float x) {
    float w = -log1pf(-__fmul_rn(x, x));
    float p;
    if (w < 5.0f) {
        w = __fadd_rn(w, -2.5f);
        p = 2.81022636e-08f;
        p = __fadd_rn(__fmul_rn(p, w),  3.43273939e-07f);
        p = __fadd_rn(__fmul_rn(p, w), -3.5233877e-06f);
        p = __fadd_rn(__fmul_rn(p, w), -4.39150654e-06f);
        p = __fadd_rn(__fmul_rn(p, w),  0.00021858087f);
        p = __fadd_rn(__fmul_rn(p, w), -0.00125372503f);
        p = __fadd_rn(__fmul_rn(p, w), -0.00417768164f);
        p = __fadd_rn(__fmul_rn(p, w),  0.246640727f);
        p = __fadd_rn(__fmul_rn(p, w),  1.50140941f);
    } else {
        w = __fadd_rn(__fsqrt_rn(w), -3.0f);
        p = -0.000200214257f;
        p = __fadd_rn(__fmul_rn(p, w),  0.000100950558f);
        p = __fadd_rn(__fmul_rn(p, w),  0.00134934322f);
        p = __fadd_rn(__fmul_rn(p, w), -0.00367342844f);
        p = __fadd_rn(__fmul_rn(p, w),  0.00573950773f);
        p = __fadd_rn(__fmul_rn(p, w), -0.0076224613f);
        p = __fadd_rn(__fmul_rn(p, w),  0.00943887047f);
        p = __fadd_rn(__fmul_rn(p, w),  1.00167406f);
        p = __fadd_rn(__fmul_rn(p, w),  2.83297682f);
    }
    return __fmul_rn(p, x);
}
__device__ __forceinline__ float softplusf(float x) {
    return __fadd_rn(fmaxf(x, 0.0f), log1pf(expf(-fabsf(x))));
}

// Exact single-track sampler (original math/order).
__device__ __forceinline__ void gamma_exact(float preA, float preB, uint32_t i,
                                            float& oal, float& obe, float& oz) {
    float al = __fadd_rn(1e-6f, softplusf(preA));
    float be = __fadd_rn(1e-6f, softplusf(preB));
    float d  = __fadd_rn(__fadd_rn(al, 1.0f), -(1.0f / 3.0f));
    float cc = __fdiv_rn(1.0f, __fsqrt_rn(__fmul_rn(9.0f, d)));

    const float LO = -0.99999994f, SPAN_N = 2.0f;
    const float UMIN = 1e-7f, SPAN_U = 1.0f - 1e-7f, SQRT2 = 1.41421356f;

    float eps_s = 0.0f, u_s = 0.0f, eps0 = 0.0f, u0 = 0.0f;
    bool found = false;
#pragma unroll 1
    for (int k = 0; k < KROUNDS; ++k) {
        uint32_t idx = (uint32_t)k * GAMMA_N + i;
        uint32_t bn = gamma_bits(KEY_N0, KEY_N1, idx);
        uint32_t bu = gamma_bits(KEY_U0, KEY_U1, idx);
        float un = __fadd_rn(__fmul_rn(bits_to_u01(bn), SPAN_N), LO);
        un = fmaxf(LO, un);
        float eps = __fmul_rn(SQRT2, erfinv_xla(un));
        float uu = __fadd_rn(__fmul_rn(bits_to_u01(bu), SPAN_U), UMIN);
        uu = fmaxf(UMIN, uu);
        if (k == 0) { eps0 = eps; u0 = uu; }
        float v = __fadd_rn(1.0f, __fmul_rn(cc, eps));
        bool acc = false;
        if (v > 0.0f) {
            float e2 = __fmul_rn(eps, eps);
            float squeeze = __fadd_rn(1.0f, -__fmul_rn(__fmul_rn(0.0331f, e2), e2));
            if (uu < squeeze) acc = true;
            else {
                float v3 = __fmul_rn(__fmul_rn(v, v), v);
                float inner = __fadd_rn(__fadd_rn(1.0f, -v3), logf(v3));
                float rhs = __fadd_rn(__fmul_rn(__fmul_rn(0.5f, eps), eps),
                                      __fmul_rn(d, inner));
                if (logf(uu) < rhs) acc = true;
            }
        }
        if (acc) { eps_s = eps; u_s = uu; found = true; break; }
    }
    if (!found) { eps_s = eps0; u_s = u0; }
    float v1 = __fadd_rn(1.0f, __fmul_rn(cc, eps_s));
    float vs = __fmul_rn(v1, __fmul_rn(v1, v1));
    float t1 = logf(__fadd_rn(__fmul_rn(d, vs), 1e-6f));
    float t2 = __fdiv_rn(logf(__fadd_rn(u_s, 1e-6f)), __fadd_rn(al, 1e-6f));
    oz = __fdiv_rn(expf(__fadd_rn(t1, t2)), __fadd_rn(be, 1e-6f));
    oal = al; obe = be;
}

// ---------------------------------------------------------------------------
// mma / ldmatrix / cp.async helpers
// ---------------------------------------------------------------------------
__device__ __forceinline__ uint32_t smem_u32(const void* p) {
    uint32_t a;
    asm("{ .reg .u64 t; cvta.to.shared.u64 t, %1; cvt.u32.u64 %0, t; }"
        : "=r"(a) : "l"(p));
    return a;
}
__device__ __forceinline__ void mma_f16(float* c, const uint32_t* a,
                                        const uint32_t* b) {
    asm volatile(
        "mma.sync.aligned.m16n8k16.row.col.f32.f16.f16.f32 "
        "{%0,%1,%2,%3}, {%4,%5,%6,%7}, {%8,%9}, {%0,%1,%2,%3};"
        : "+f"(c[0]), "+f"(c[1]), "+f"(c[2]), "+f"(c[3])
        : "r"(a[0]), "r"(a[1]), "r"(a[2]), "r"(a[3]),
          "r"(b[0]), "r"(b[1]));
}
__device__ __forceinline__ void ldsm4(uint32_t& r0, uint32_t& r1,
                                      uint32_t& r2, uint32_t& r3, uint32_t a) {
    asm volatile("ldmatrix.sync.aligned.m8n8.x4.shared.b16 {%0,%1,%2,%3}, [%4];"
                 : "=r"(r0), "=r"(r1), "=r"(r2), "=r"(r3) : "r"(a));
}
__device__ __forceinline__ void cpa16(uint32_t dst, const void* src) {
    asm volatile("cp.async.cg.shared.global [%0], [%1], 16;"
                 :: "r"(dst), "l"(src));
}
__device__ __forceinline__ void split_h2(float x, float y,
                                         __half2& hi, __half2& lo) {
    hi = __floats2half2_rn(x, y);
    float2 b = __half22float2(hi);
    lo = __floats2half2_rn(__fadd_rn(x, -b.x), __fadd_rn(y, -b.y));
}
__device__ __forceinline__ uint32_t swz(int row, int q) {
    return (uint32_t)(((row >> 1) << 7) +
                      (((((row & 1) << 2) | q) ^ ((row >> 1) & 7)) << 4));
}

// ---------------------------------------------------------------------------
// GEMM: C[M,N] = act(A[M,K] @ Bt[N,K]^T + bias)
//   NPROD 3/2/1 as before. ACT: 0 fp32 (partials if SPLITK); 1 relu half hi
//   (WRLO +lo); 2 softplus-split. SPLITK: z selects K-window; partial plane
//   stride = ldc * (gridDim.y*128). IDX: gather A rows via g_flags.
// ---------------------------------------------------------------------------
#define PLANEB 8192
#define STAGEB (4 * PLANEB)
#define NSTAGE 3

template <int ACT, int NPROD, int WRLO, int SPLITK, int IDX>
__global__ __launch_bounds__(256, 2)
void mma_gemm(const __half* __restrict__ Ahg, const __half* __restrict__ Alg,
              const __half* __restrict__ Bhg, const __half* __restrict__ Blg,
              const float* __restrict__ bias,
              __half* __restrict__ Chg, __half* __restrict__ Clg,
              float* __restrict__ C, float* __restrict__ C2,
              int K, int lda, int ldc) {
    extern __shared__ __half smh[];
    __shared__ float s_bias[128];

    const int tid  = threadIdx.x;
    const int wid  = tid >> 5;
    const int lane = tid & 31;
    const int qr   = lane >> 2;
    const int qc   = lane & 3;
    const int grp  = lane >> 3;
    const int lr   = lane & 7;
    const int m_w  = (wid >> 2) * 64;
    const int n_w  = (wid & 3) * 32;
    const int row0 = blockIdx.y * 128;
    const int col0 = blockIdx.x * 128;
    const int kb   = SPLITK ? ((int)blockIdx.z * K) : 0;

    if (tid < 128) s_bias[tid] = bias[col0 + tid];

    const uint32_t smb = smem_u32(smh);

    float acc[4][4][4];
#pragma unroll
    for (int a = 0; a < 4; ++a)
#pragma unroll
        for (int b = 0; b < 4; ++b)
#pragma unroll
            for (int c = 0; c < 4; ++c) acc[a][b][c] = 0.0f;

    const int NCH  = K >> 5;
    const int r_ld = tid >> 1;
    const int q0   = (tid & 1) * 2;

    int growA;
    if (IDX) {
        uint32_t fe = g_flags[row0 + r_ld];
        growA = min((int)(fe >> 6), 8191);
    } else {
        growA = row0 + r_ld;
    }
    const int growB = col0 + r_ld;
    const uint32_t d_sw0 = swz(r_ld, q0);
    const uint32_t d_sw1 = swz(r_ld, q0 + 1);

    auto issue = [&](int stage, int kchunk) {
        const int k0 = kb + (kchunk << 5);
        const uint32_t sbase = smb + (uint32_t)(stage * STAGEB);
        {
            const __half* s = Ahg + (size_t)growA * lda + k0 + q0 * 8;
            cpa16(sbase + d_sw0, s);
            cpa16(sbase + d_sw1, s + 8);
        }
        if (NPROD == 3) {
            const __half* s = Alg + (size_t)growA * lda + k0 + q0 * 8;
            cpa16(sbase + (uint32_t)PLANEB + d_sw0, s);
            cpa16(sbase + (uint32_t)PLANEB + d_sw1, s + 8);
        }
        {
            const __half* s = Bhg + (size_t)growB * lda + k0 + q0 * 8;
            cpa16(sbase + (uint32_t)(2 * PLANEB) + d_sw0, s);
            cpa16(sbase + (uint32_t)(2 * PLANEB) + d_sw1, s + 8);
        }
        if (NPROD >= 2) {
            const __half* s = Blg + (size_t)growB * lda + k0 + q0 * 8;
            cpa16(sbase + (uint32_t)(3 * PLANEB) + d_sw0, s);
            cpa16(sbase + (uint32_t)(3 * PLANEB) + d_sw1, s + 8);
        }
        asm volatile("cp.async.commit_group;" ::: "memory");
    };

    issue(0, 0);
    if (NCH > 1) {
        issue(1, 1);
        asm volatile("cp.async.wait_group 1;" ::: "memory");
    } else {
        asm volatile("cp.async.wait_group 0;" ::: "memory");
    }
    __syncthreads();

    for (int i = 0; i < NCH; ++i) {
        if (i + 2 < NCH) issue((i + 2) % NSTAGE, i + 2);

        const uint32_t sb = smb + (uint32_t)((i % NSTAGE) * STAGEB);
#pragma unroll
        for (int ks = 0; ks < 2; ++ks) {
            uint32_t bh[4][2], bl[4][2];
#pragma unroll
            for (int nn = 0; nn < 2; ++nn) {
                const int rB = n_w + nn * 16 + (grp >> 1) * 8 + lr;
                const int qB = ks * 2 + (grp & 1);
                const uint32_t ab = sb + (uint32_t)(2 * PLANEB) + swz(rB, qB);
                ldsm4(bh[2 * nn][0], bh[2 * nn][1],
                      bh[2 * nn + 1][0], bh[2 * nn + 1][1], ab);
                if (NPROD >= 2)
                    ldsm4(bl[2 * nn][0], bl[2 * nn][1],
                          bl[2 * nn + 1][0], bl[2 * nn + 1][1],
                          ab + (uint32_t)PLANEB);
            }
#pragma unroll
            for (int mt = 0; mt < 4; ++mt) {
                uint32_t ah[4], al[4];
                const int rA = m_w + mt * 16 + (grp & 1) * 8 + lr;
                const int qA = ks * 2 + (grp >> 1);
                const uint32_t aa = sb + swz(rA, qA);
                ldsm4(ah[0], ah[1], ah[2], ah[3], aa);
                if (NPROD == 3)
                    ldsm4(al[0], al[1], al[2], al[3], aa + (uint32_t)PLANEB);
#pragma unroll
                for (int nt = 0; nt < 4; ++nt) {
                    mma_f16(acc[mt][nt], ah, bh[nt]);
                    if (NPROD >= 2) mma_f16(acc[mt][nt], ah, bl[nt]);
                    if (NPROD == 3) mma_f16(acc[mt][nt], al, bh[nt]);
                }
            }
        }

        if (i + 1 < NCH) {
            if (i + 2 < NCH) {
                asm volatile("cp.async.wait_group 1;" ::: "memory");
            } else {
                asm volatile("cp.async.wait_group 0;" ::: "memory");
            }
            __syncthreads();
        }
    }

    float* Cz = C;
    if (SPLITK)
        Cz = C + (size_t)blockIdx.z * ((size_t)ldc * ((size_t)gridDim.y << 7));
#pragma unroll
    for (int mt = 0; mt < 4; ++mt) {
        int r = row0 + m_w + mt * 16 + qr;
#pragma unroll
        for (int nt = 0; nt < 4; ++nt) {
            int lc = n_w + nt * 8 + 2 * qc;
            int gc = col0 + lc;
            float2 t0, t1;
            float b0v = SPLITK ? 0.0f : s_bias[lc];
            float b1v = SPLITK ? 0.0f : s_bias[lc + 1];
            t0.x = acc[mt][nt][0] + b0v;
            t0.y = acc[mt][nt][1] + b1v;
            t1.x = acc[mt][nt][2] + b0v;
            t1.y = acc[mt][nt][3] + b1v;
            if (ACT == 1) {
                t0.x = fmaxf(t0.x, 0.0f); t0.y = fmaxf(t0.y, 0.0f);
                t1.x = fmaxf(t1.x, 0.0f); t1.y = fmaxf(t1.y, 0.0f);
                if (WRLO) {
                    __half2 h2, l2;
                    split_h2(t0.x, t0.y, h2, l2);
                    *reinterpret_cast<__half2*>(&Chg[(size_t)r * ldc + gc]) = h2;
                    *reinterpret_cast<__half2*>(&Clg[(size_t)r * ldc + gc]) = l2;
                    split_h2(t1.x, t1.y, h2, l2);
                    *reinterpret_cast<__half2*>(&Chg[(size_t)(r + 8) * ldc + gc]) = h2;
                    *reinterpret_cast<__half2*>(&Clg[(size_t)(r + 8) * ldc + gc]) = l2;
                } else {
                    *reinterpret_cast<__half2*>(&Chg[(size_t)r * ldc + gc]) =
                        __floats2half2_rn(t0.x, t0.y);
                    *reinterpret_cast<__half2*>(&Chg[(size_t)(r + 8) * ldc + gc]) =
                        __floats2half2_rn(t1.x, t1.y);
                }
            } else if (ACT == 2) {
                t0.x = __fadd_rn(1e-6f, softplusf(t0.x));
                t0.y = __fadd_rn(1e-6f, softplusf(t0.y));
                t1.x = __fadd_rn(1e-6f, softplusf(t1.x));
                t1.y = __fadd_rn(1e-6f, softplusf(t1.y));
                if (gc < 2048) {
                    *reinterpret_cast<float2*>(&C [(size_t)r * 2048 + gc]) = t0;
                    *reinterpret_cast<float2*>(&C [(size_t)(r + 8) * 2048 + gc]) = t1;
                } else {
                    *reinterpret_cast<float2*>(&C2[(size_t)r * 2048 + gc - 2048]) = t0;
                    *reinterpret_cast<float2*>(&C2[(size_t)(r + 8) * 2048 + gc - 2048]) = t1;
                }
            } else {
                *reinterpret_cast<float2*>(&Cz[(size_t)r * ldc + gc]) = t0;
                *reinterpret_cast<float2*>(&Cz[(size_t)(r + 8) * ldc + gc]) = t1;
            }
        }
    }
}

// ---------------------------------------------------------------------------
// Fixup combine: out = relu(sum_s partial + bias) -> half hi/lo planes.
// ---------------------------------------------------------------------------
__global__ __launch_bounds__(256)
void fix_combine(const float* __restrict__ P, int S, int N,
                 const float* __restrict__ bias,
                 __half* __restrict__ oh, __half* __restrict__ ol) {
    int t = blockIdx.x * 256 + threadIdx.x;     // half2 index
    if (t >= 512 * N / 2) return;
    int e = t * 2;
    int r = e / N, c = e % N;
    float a = 0.0f, b = 0.0f;
    for (int s = 0; s < S; ++s) {
        const float* p = P + (size_t)s * 512 * N + (size_t)r * N + c;
        a += p[0];
        b += p[1];
    }
    a = fmaxf(a + bias[c], 0.0f);
    b = fmaxf(b + bias[c + 1], 0.0f);
    __half2 h, l;
    split_h2(a, b, h, l);
    *reinterpret_cast<__half2*>(&oh[(size_t)r * N + c]) = h;
    *reinterpret_cast<__half2*>(&ol[(size_t)r * N + c]) = l;
}

// ---------------------------------------------------------------------------
// Merged prep: weights + x-split + bias + flag reset.
// ---------------------------------------------------------------------------
struct PrepJobs {
    const float* W[9];
    __half* Wh[9];
    __half* Wl[9];
    int K[9], N[9], start[9], wl[9];
    int wtiles;
    const float* X;
    __half* Xh; __half* Xl;
    int xblocks;
    const float* hb1; const float* hb2;
    float* bh;
};

__global__ __launch_bounds__(256)
void prep_all(PrepJobs j) {
    int b = blockIdx.x;
    if (b < j.wtiles) {
        int ji = 0;
#pragma unroll
        for (int s = 1; s < 9; ++s)
            if (b >= j.start[s]) ji = s;
        const float* W = j.W[ji];
        __half* Wh = j.Wh[ji];
        __half* Wl = j.Wl[ji];
        int K = j.K[ji], N = j.N[ji];
        int wl = j.wl[ji];
        int t = b - j.start[ji];
        int ntn = N >> 5;
        int n0 = (t % ntn) << 5, k0 = (t / ntn) << 5;

        __shared__ float s[32][33];
        int tt = threadIdx.x;
        int a = tt >> 5, bb = tt & 31;
#pragma unroll
        for (int p = 0; p < 4; ++p) {
            int k = p * 8 + a;
            s[k][bb] = W[(size_t)(k0 + k) * N + n0 + bb];
        }
        __syncthreads();
#pragma unroll
        for (int p = 0; p < 4; ++p) {
            int n = p * 8 + a;
            float v = s[bb][n];
            __half h = __float2half_rn(v);
            Wh[(size_t)(n0 + n) * K + k0 + bb] = h;
            if (wl)
                Wl[(size_t)(n0 + n) * K + k0 + bb] =
                    __float2half_rn(__fadd_rn(v, -__half2float(h)));
        }
        return;
    }
    b -= j.wtiles;
    if (b < j.xblocks) {
        int t = b * 256 + threadIdx.x;
        float4 v = reinterpret_cast<const float4*>(j.X)[t];
        __half2 h0, l0, h1, l1;
        split_h2(v.x, v.y, h0, l0);
        split_h2(v.z, v.w, h1, l1);
        reinterpret_cast<__half2*>(j.Xh)[2 * t]     = h0;
        reinterpret_cast<__half2*>(j.Xh)[2 * t + 1] = h1;
        reinterpret_cast<__half2*>(j.Xl)[2 * t]     = l0;
        reinterpret_cast<__half2*>(j.Xl)[2 * t + 1] = l1;
        return;
    }
    int t = threadIdx.x;
    if (t < 128) j.bh[t] = (t < 64) ? j.hb1[t] : j.hb2[t - 64];
    g_flags[t] = 0u;
    g_flags[t + 256] = 0u;
    if (t == 0) g_nflag = 0u;
}

// ---------------------------------------------------------------------------
// Gamma sampler with +-tau decision-stability test.
// ---------------------------------------------------------------------------
__global__ __launch_bounds__(256)
void gamma_sampler(const float* __restrict__ pre, const float* __restrict__ bh,
                   float* __restrict__ out_la, float* __restrict__ out_lb,
                   float* __restrict__ out_z, __half* __restrict__ zh) {
    int i = blockIdx.x * blockDim.x + threadIdx.x;
    if (i >= BATCHN * LATENT) return;
    int row = i >> 6, lat = i & 63;

    const float* p1 = pre + 8192ull * 128;
    float preA = (pre[row * 128 + lat]      + p1[row * 128 + lat])      + bh[lat];
    float preB = (pre[row * 128 + 64 + lat] + p1[row * 128 + 64 + lat]) + bh[64 + lat];

    float al3[3], d3[3], cc3[3];
    al3[0] = __fadd_rn(1e-6f, softplusf(preA - TAU));
    al3[1] = __fadd_rn(1e-6f, softplusf(preA));
    al3[2] = __fadd_rn(1e-6f, softplusf(preA + TAU));
#pragma unroll
    for (int t = 0; t < 3; ++t) {
        d3[t]  = __fadd_rn(__fadd_rn(al3[t], 1.0f), -(1.0f / 3.0f));
        cc3[t] = __fdiv_rn(1.0f, __fsqrt_rn(__fmul_rn(9.0f, d3[t])));
    }
    float be = __fadd_rn(1e-6f, softplusf(preB));

    const float LO = -0.99999994f, SPAN_N = 2.0f;
    const float UMIN = 1e-7f, SPAN_U = 1.0f - 1e-7f, SQRT2 = 1.41421356f;

    int kk[3] = {-1, -1, -1};
    float es1 = 0.0f, us1 = 0.0f, eps0 = 0.0f, u0 = 0.0f;

#pragma unroll 1
    for (int k = 0; k < KROUNDS; ++k) {
        if (kk[0] >= 0 && kk[1] >= 0 && kk[2] >= 0) break;
        uint32_t idx = (uint32_t)k * GAMMA_N + (uint32_t)i;
        uint32_t bn = gamma_bits(KEY_N0, KEY_N1, idx);
        uint32_t bu = gamma_bits(KEY_U0, KEY_U1, idx);

        float un = __fadd_rn(__fmul_rn(bits_to_u01(bn), SPAN_N), LO);
        un = fmaxf(LO, un);
        float eps = __fmul_rn(SQRT2, erfinv_xla(un));
        float uu = __fadd_rn(__fmul_rn(bits_to_u01(bu), SPAN_U), UMIN);
        uu = fmaxf(UMIN, uu);
        if (k == 0) { eps0 = eps; u0 = uu; }

        float e2 = __fmul_rn(eps, eps);
        float squeeze = __fadd_rn(1.0f, -__fmul_rn(__fmul_rn(0.0331f, e2), e2));
        float lu = logf(uu);
#pragma unroll
        for (int t = 0; t < 3; ++t) {
            if (kk[t] >= 0) continue;
            float v = __fadd_rn(1.0f, __fmul_rn(cc3[t], eps));
            bool acc = false;
            if (v > 0.0f) {
                if (uu < squeeze) acc = true;
                else {
                    float v3 = __fmul_rn(__fmul_rn(v, v), v);
                    float inner = __fadd_rn(__fadd_rn(1.0f, -v3), logf(v3));
                    float rhs = __fadd_rn(__fmul_rn(__fmul_rn(0.5f, eps), eps),
                                          __fmul_rn(d3[t], inner));
                    if (lu < rhs) acc = true;
                }
            }
            if (acc) {
                kk[t] = k;
                if (t == 1) { es1 = eps; us1 = uu; }
            }
        }
    }

    float eps_s, u_s;
    if (kk[1] >= 0) { eps_s = es1; u_s = us1; }
    else            { eps_s = eps0; u_s = u0; }

    float v1 = __fadd_rn(1.0f, __fmul_rn(cc3[1], eps_s));
    float vs = __fmul_rn(v1, __fmul_rn(v1, v1));
    float t1 = logf(__fadd_rn(__fmul_rn(d3[1], vs), 1e-6f));
    float t2 = __fdiv_rn(logf(__fadd_rn(u_s, 1e-6f)), __fadd_rn(al3[1], 1e-6f));
    float z  = __fdiv_rn(expf(__fadd_rn(t1, t2)), __fadd_rn(be, 1e-6f));

    out_la[i] = al3[1];
    out_lb[i] = be;
    out_z[i]  = z;
    zh[i] = __float2half_rn(z);

    if (!(kk[0] == kk[1] && kk[1] == kk[2])) {
        uint32_t pos = atomicAdd(&g_nflag, 1u);
        if (pos < MAXFLAG) g_flags[pos] = (uint32_t)i;
    }
}

// Fixup sampler: sums 8 head partials + bias, exact re-sample, overwrite.
__global__ __launch_bounds__(256)
void fixup_sampler(const float* __restrict__ pref, const float* __restrict__ bh,
                   float* __restrict__ out_la, float* __restrict__ out_lb,
                   float* __restrict__ out_z, __half* __restrict__ zh) {
    uint32_t pos = blockIdx.x * 256 + threadIdx.x;
    uint32_t n = g_nflag;
    if (n > MAXFLAG) n = MAXFLAG;
    if (pos >= n) return;
    uint32_t i = g_flags[pos];
    int lat = (int)(i & 63u);
    float preA = 0.0f, preB = 0.0f;
#pragma unroll
    for (int s = 0; s < 8; ++s) {
        const float* p = pref + (size_t)s * 512 * 128 + (size_t)pos * 128;
        preA += p[lat];
        preB += p[64 + lat];
    }
    preA += bh[lat];
    preB += bh[64 + lat];
    float al, be, z;
    gamma_exact(preA, preB, i, al, be, z);
    out_la[i] = al;
    out_lb[i] = be;
    out_z[i]  = z;
    zh[i] = __float2half_rn(z);
}

// ---------------------------------------------------------------------------
// Launch
// ---------------------------------------------------------------------------
extern "C" void kernel_launch(void* const* d_in, const int* in_sizes, int n_in,
                              void* d_out, int out_size) {
    (void)in_sizes; (void)n_in; (void)out_size;

    const float* x    = (const float*)d_in[0];
    const float* f1w  = (const float*)d_in[1];
    const float* f1b  = (const float*)d_in[2];
    const float* f2w  = (const float*)d_in[3];
    const float* f2b  = (const float*)d_in[4];
    const float* f3w  = (const float*)d_in[5];
    const float* f3b  = (const float*)d_in[6];
    const float* f41w = (const float*)d_in[7];
    const float* f41b = (const float*)d_in[8];
    const float* f42w = (const float*)d_in[9];
    const float* f42b = (const float*)d_in[10];
    const float* f4w  = (const float*)d_in[11];
    const float* f4b  = (const float*)d_in[12];
    const float* f5w  = (const float*)d_in[13];
    const float* f5b  = (const float*)d_in[14];
    const float* f6w  = (const float*)d_in[15];
    const float* f6b  = (const float*)d_in[16];
    const float* f7w  = (const float*)d_in[17];
    const float* f7b  = (const float*)d_in[18];

    float* out = (float*)d_out;
    const size_t OFF_BE = 8192ull * 2048;
    const size_t OFF_LA = 2 * OFF_BE;
    const size_t OFF_LB = OFF_LA + 524288;
    const size_t OFF_Z  = OFF_LB + 524288;

    __half *xh, *xl, *b0h, *b1h, *zh, *wh, *wl;
    __half *f1h, *f1l, *f2h, *f2l, *f3h, *f3l;
    float *pre, *bh, *fxp;
    cudaGetSymbolAddress((void**)&xh,  g_xh);
    cudaGetSymbolAddress((void**)&xl,  g_xl);
    cudaGetSymbolAddress((void**)&b0h, g_b0h);
    cudaGetSymbolAddress((void**)&b1h, g_b1h);
    cudaGetSymbolAddress((void**)&zh,  g_zh);
    cudaGetSymbolAddress((void**)&wh,  g_wh);
    cudaGetSymbolAddress((void**)&wl,  g_wl);
    cudaGetSymbolAddress((void**)&pre, g_pre);
    cudaGetSymbolAddress((void**)&bh,  g_bh);
    cudaGetSymbolAddress((void**)&f1h, g_f1h);
    cudaGetSymbolAddress((void**)&f1l, g_f1l);
    cudaGetSymbolAddress((void**)&f2h, g_f2h);
    cudaGetSymbolAddress((void**)&f2l, g_f2l);
    cudaGetSymbolAddress((void**)&f3h, g_f3h);
    cudaGetSymbolAddress((void**)&f3l, g_f3l);
    cudaGetSymbolAddress((void**)&fxp, g_fxp);

    constexpr int DYN = NSTAGE * STAGEB;   // 98304 bytes
    cudaFuncSetAttribute((const void*)mma_gemm<1, 2, 0, 0, 0>, cudaFuncAttributeMaxDynamicSharedMemorySize, DYN);
    cudaFuncSetAttribute((const void*)mma_gemm<0, 2, 0, 1, 0>, cudaFuncAttributeMaxDynamicSharedMemorySize, DYN);
    cudaFuncSetAttribute((const void*)mma_gemm<0, 3, 0, 1, 1>, cudaFuncAttributeMaxDynamicSharedMemorySize, DYN);
    cudaFuncSetAttribute((const void*)mma_gemm<0, 3, 0, 1, 0>, cudaFuncAttributeMaxDynamicSharedMemorySize, DYN);
    cudaFuncSetAttribute((const void*)mma_gemm<1, 1, 0, 0, 0>, cudaFuncAttributeMaxDynamicSharedMemorySize, DYN);
    cudaFuncSetAttribute((const void*)mma_gemm<2, 1, 0, 0, 0>, cudaFuncAttributeMaxDynamicSharedMemorySize, DYN);

    // ---- merged prep ----
    PrepJobs jp = {};
    int st = 0;
    auto add = [&](int idx, const float* W, uint32_t off, int K, int N, int wlf) {
        jp.W[idx] = W; jp.Wh[idx] = wh + off; jp.Wl[idx] = wl + off;
        jp.K[idx] = K; jp.N[idx] = N; jp.start[idx] = st; jp.wl[idx] = wlf;
        st += (N >> 5) * (K >> 5);
    };
    add(0, f1w,  OW1, 2048, 1024, 1);
    add(1, f2w,  OW2, 1024, 1024, 1);
    add(2, f3w,  OW3, 1024, 2048, 1);
    add(3, f41w, OWH, 2048, 64,   1);
    add(4, f42w, OWH + 64 * 2048, 2048, 64, 1);
    add(5, f4w,  OW4, 64,   2048, 0);
    add(6, f5w,  OW5, 2048, 1024, 0);
    add(7, f6w,  OW6, 1024, 1024, 0);
    add(8, f7w,  OW7, 1024, 4096, 0);
    jp.wtiles = st;
    jp.X = x; jp.Xh = xh; jp.Xl = xl;
    jp.xblocks = (8192 * 2048 / 4) / 256;
    jp.hb1 = f41b; jp.hb2 = f42b; jp.bh = bh;
    prep_all<<<jp.wtiles + jp.xblocks + 1, 256>>>(jp);

    // ---- encoder (2-product) ----
    mma_gemm<1, 2, 0, 0, 0><<<dim3( 8, 64), 256, DYN>>>(xh,  nullptr, wh + OW1, wl + OW1, f1b, b0h, nullptr, nullptr, nullptr, 2048, 2048, 1024);
    mma_gemm<1, 2, 0, 0, 0><<<dim3( 8, 64), 256, DYN>>>(b0h, nullptr, wh + OW2, wl + OW2, f2b, b1h, nullptr, nullptr, nullptr, 1024, 1024, 1024);
    mma_gemm<1, 2, 0, 0, 0><<<dim3(16, 64), 256, DYN>>>(b1h, nullptr, wh + OW3, wl + OW3, f3b, b0h, nullptr, nullptr, nullptr, 1024, 1024, 2048);
    // heads split-K=2 (2-product) -> pre partials
    mma_gemm<0, 2, 0, 1, 0><<<dim3(1, 64, 2), 256, DYN>>>(b0h, nullptr, wh + OWH, wl + OWH, bh, nullptr, nullptr, pre, nullptr, 1024, 2048, 128);
    // ---- gamma sampler with stability flagging ----
    gamma_sampler<<<(BATCHN * LATENT) / 256, 256>>>(
        pre, bh, out + OFF_LA, out + OFF_LB, out + OFF_Z, zh);
    // ---- fixup: 3-product gathered encoder chain, split-K everywhere ----
    mma_gemm<0, 3, 0, 1, 1><<<dim3( 8, 4, 8), 256, DYN>>>(xh,  xl,  wh + OW1, wl + OW1, f1b, nullptr, nullptr, fxp, nullptr, 256, 2048, 1024);
    fix_combine<<<1024, 256>>>(fxp, 8, 1024, f1b, f1h, f1l);
    mma_gemm<0, 3, 0, 1, 0><<<dim3( 8, 4, 4), 256, DYN>>>(f1h, f1l, wh + OW2, wl + OW2, f2b, nullptr, nullptr, fxp, nullptr, 256, 1024, 1024);
    fix_combine<<<1024, 256>>>(fxp, 4, 1024, f2b, f2h, f2l);
    mma_gemm<0, 3, 0, 1, 0><<<dim3(16, 4, 4), 256, DYN>>>(f2h, f2l, wh + OW3, wl + OW3, f3b, nullptr, nullptr, fxp, nullptr, 256, 1024, 2048);
    fix_combine<<<2048, 256>>>(fxp, 4, 2048, f3b, f3h, f3l);
    mma_gemm<0, 3, 0, 1, 0><<<dim3( 1, 4, 8), 256, DYN>>>(f3h, f3l, wh + OWH, wl + OWH, bh, nullptr, nullptr, fxp, nullptr, 256, 2048, 128);
    fixup_sampler<<<2, 256>>>(fxp, bh, out + OFF_LA, out + OFF_LB, out + OFF_Z, zh);
    // ---- decoder (1-product) ----
    mma_gemm<1, 1, 0, 0, 0><<<dim3(16, 64), 256, DYN>>>(zh,  nullptr, wh + OW4, nullptr, f4b, b1h, nullptr, nullptr, nullptr, 64, 64, 2048);
    mma_gemm<1, 1, 0, 0, 0><<<dim3( 8, 64), 256, DYN>>>(b1h, nullptr, wh + OW5, nullptr, f5b, b0h, nullptr, nullptr, nullptr, 2048, 2048, 1024);
    mma_gemm<1, 1, 0, 0, 0><<<dim3( 8, 64), 256, DYN>>>(b0h, nullptr, wh + OW6, nullptr, f6b, b1h, nullptr, nullptr, nullptr, 1024, 1024, 1024);
    mma_gemm<2, 1, 0, 0, 0><<<dim3(32, 64), 256, DYN>>>(b1h, nullptr, wh + OW7, nullptr, f7b, nullptr, nullptr, out, out + OFF_BE, 1024, 1024, 2048);
}